// round 14
// baseline (speedup 1.0000x reference)
#include <cuda_runtime.h>
#include <cuda_fp16.h>
#include <math.h>
#include <stdint.h>
#include <stddef.h>

#define D_MODEL 512
#define NH      8
#define HD      64
#define DFF     2048
#define BATCH   2
#define SEQ     2048
#define NTOK    (BATCH * SEQ)   // 4096
#define QKV_LD  (3 * D_MODEL)   // 1536
#define NSPLIT  4

// ---------------- scratch (no allocation allowed) ----------------
__device__ __half g_xn [NTOK * D_MODEL];
__device__ __half g_qkv[NTOK * QKV_LD];
__device__ __half g_ctx[NTOK * D_MODEL];
__device__ __half g_xn2[NTOK * D_MODEL];
__device__ __half g_h  [NTOK * DFF];
__device__ float  g_x1 [NTOK * D_MODEL];
__device__ __half g_opart[NSPLIT * NTOK * D_MODEL];   // split-KV partial O (fp16)
__device__ float  g_lpart[NSPLIT * BATCH * NH * SEQ]; // split-KV partial l
// converted (fp16) weights: wqkv | wo | w1 | w2
#define WR_QKV 0
#define WR_O   (QKV_LD * D_MODEL)
#define WR_1   (WR_O + D_MODEL * D_MODEL)
#define WR_2   (WR_1 + DFF * D_MODEL)
#define WR_TOT (WR_2 + D_MODEL * DFF)
__device__ __half g_wr[WR_TOT];

#define LOG2E 1.4426950408889634f
#define ONES2 0x3C003C00u   // half2(1.0, 1.0)
#define SMAX0 3.0f          // fixed softmax max (exp2 domain); cancels in O/l

// ---------------- helpers ----------------
__device__ __forceinline__ uint32_t h2u(__half2 h) {
    return *reinterpret_cast<uint32_t*>(&h);
}
__device__ __forceinline__ __half2 u2h(uint32_t u) {
    return *reinterpret_cast<__half2*>(&u);
}

__device__ __forceinline__ void mma_f16(float (&d)[4], const uint32_t (&a)[4],
                                        const uint32_t (&b)[2]) {
    asm volatile(
        "mma.sync.aligned.m16n8k16.row.col.f32.f16.f16.f32 "
        "{%0,%1,%2,%3}, {%4,%5,%6,%7}, {%8,%9}, {%0,%1,%2,%3};\n"
        : "+f"(d[0]), "+f"(d[1]), "+f"(d[2]), "+f"(d[3])
        : "r"(a[0]), "r"(a[1]), "r"(a[2]), "r"(a[3]), "r"(b[0]), "r"(b[1]));
}

__device__ __forceinline__ void mma_h16(uint32_t (&d)[2], const uint32_t (&a)[4],
                                        const uint32_t (&b)[2]) {
    asm volatile(
        "mma.sync.aligned.m16n8k16.row.col.f16.f16.f16.f16 "
        "{%0,%1}, {%2,%3,%4,%5}, {%6,%7}, {%0,%1};\n"
        : "+r"(d[0]), "+r"(d[1])
        : "r"(a[0]), "r"(a[1]), "r"(a[2]), "r"(a[3]), "r"(b[0]), "r"(b[1]));
}

__device__ __forceinline__ void ldsm_x4(uint32_t& r0, uint32_t& r1, uint32_t& r2,
                                        uint32_t& r3, uint32_t addr) {
    asm volatile("ldmatrix.sync.aligned.m8n8.x4.shared.b16 {%0,%1,%2,%3}, [%4];\n"
                 : "=r"(r0), "=r"(r1), "=r"(r2), "=r"(r3) : "r"(addr));
}

__device__ __forceinline__ void ldsm_x4_trans(uint32_t& r0, uint32_t& r1, uint32_t& r2,
                                              uint32_t& r3, uint32_t addr) {
    asm volatile("ldmatrix.sync.aligned.m8n8.x4.trans.shared.b16 {%0,%1,%2,%3}, [%4];\n"
                 : "=r"(r0), "=r"(r1), "=r"(r2), "=r"(r3) : "r"(addr));
}

__device__ __forceinline__ uint32_t ex2_h2(uint32_t x) {
    uint32_t r;
    asm("ex2.approx.f16x2 %0, %1;\n" : "=r"(r) : "r"(x));
    return r;
}

__device__ __forceinline__ void cp_async16(void* smem_dst, const void* gsrc) {
    uint32_t s = (uint32_t)__cvta_generic_to_shared(smem_dst);
    asm volatile("cp.async.cg.shared.global [%0], [%1], 16;\n" :: "r"(s), "l"(gsrc));
}
__device__ __forceinline__ void cp_commit() {
    asm volatile("cp.async.commit_group;\n");
}
template <int N>
__device__ __forceinline__ void cp_wait() {
    asm volatile("cp.async.wait_group %0;\n" :: "n"(N));
}

// ---------------- fused weight f32 -> f16 (all 4 weights, 1 launch) --------
#define N8_QKV (QKV_LD * D_MODEL / 8)
#define N8_O   (D_MODEL * D_MODEL / 8)
#define N8_1   (DFF * D_MODEL / 8)
#define N8_2   (D_MODEL * DFF / 8)
#define N8_TOT (N8_QKV + N8_O + N8_1 + N8_2)   // 393216 = 1536*256

__global__ __launch_bounds__(256) void cvtw_all(const float* __restrict__ wqkv,
                                                const float* __restrict__ wo,
                                                const float* __restrict__ w1,
                                                const float* __restrict__ w2,
                                                __half* __restrict__ d) {
    const int i = blockIdx.x * 256 + threadIdx.x;
    int j = i;
    const float* s;
    if (j < N8_QKV) { s = wqkv; }
    else {
        j -= N8_QKV;
        if (j < N8_O) { s = wo; }
        else {
            j -= N8_O;
            if (j < N8_1) { s = w1; }
            else { j -= N8_1; s = w2; }
        }
    }
    const float4 v0 = ((const float4*)s)[2 * j];
    const float4 v1 = ((const float4*)s)[2 * j + 1];
    uint4 o;
    o.x = h2u(__floats2half2_rn(v0.x, v0.y));
    o.y = h2u(__floats2half2_rn(v0.z, v0.w));
    o.z = h2u(__floats2half2_rn(v1.x, v1.y));
    o.w = h2u(__floats2half2_rn(v1.z, v1.w));
    ((uint4*)d)[i] = o;
}

// ---------------- RMSNorm: f32 in, f16 out ----------------
__global__ __launch_bounds__(128) void rmsnorm_k(const float* __restrict__ x,
                                                 const float* __restrict__ sc,
                                                 __half* __restrict__ o) {
    const int row = blockIdx.x;
    const int t = threadIdx.x;
    const float4 v = ((const float4*)(x + (size_t)row * D_MODEL))[t];
    float ss = v.x * v.x + v.y * v.y + v.z * v.z + v.w * v.w;
#pragma unroll
    for (int ofs = 16; ofs; ofs >>= 1)
        ss += __shfl_xor_sync(0xffffffffu, ss, ofs);
    __shared__ float ws[4];
    if ((t & 31) == 0) ws[t >> 5] = ss;
    __syncthreads();
    const float tot = ws[0] + ws[1] + ws[2] + ws[3];
    const float r = rsqrtf(tot * (1.0f / D_MODEL) + 1e-8f);
    const float4 s4 = ((const float4*)sc)[t];
    uint2 u;
    u.x = h2u(__floats2half2_rn(v.x * s4.x * r, v.y * s4.y * r));
    u.y = h2u(__floats2half2_rn(v.z * s4.z * r, v.w * s4.w * r));
    ((uint2*)(o + (size_t)row * D_MODEL))[t] = u;
}

// ---------------- FP16 tensor-core GEMM, ldmatrix fragments ----------------
// C[N,M] = A[N,K] @ W[M,K]^T + bias. Row tile TM (128 or 64), col tile 128.
// EPI: 1 = GELU -> half, 2 = +res -> float, 3 = qkv (scale q cols) -> half
#define GSTRIDE 36   // uint32 (half2) units per row: 32 data + 4 pad
template <int EPI, int TM>
__global__ __launch_bounds__(256, 2) void gemm_h(const __half* __restrict__ A,
                                                 const __half* __restrict__ W,
                                                 const float* __restrict__ bias,
                                                 const float* __restrict__ res,
                                                 void* __restrict__ Cv,
                                                 int N, int M, int K) {
    constexpr int MT = TM / 32;            // m16 tiles per warp
    extern __shared__ uint32_t smu[];

    const int t = threadIdx.x;
    const int lane = t & 31;
    const int warp = t >> 5;
    const int wm = warp & 1;
    const int wn = warp >> 1;
    const int grp = lane >> 2;
    const int tig = lane & 3;

    const int bm = blockIdx.y * TM;
    const int bn = blockIdx.x * 128;

    const int crow = t >> 3;
    const int cchk = t & 7;
    const __half* gA = A + (size_t)(bm + crow) * K + cchk * 8;
    const __half* gW = W + (size_t)(bn + crow) * K + cchk * 8;
    uint32_t* sAp = smu + crow * GSTRIDE + cchk * 4;
    uint32_t* sWp = smu + 2 * TM * GSTRIDE + crow * GSTRIDE + cchk * 4;

    const uint32_t smem0 = (uint32_t)__cvta_generic_to_shared(smu);
    const uint32_t aAddr0 = smem0 +
        (((wm * (TM / 2) + (lane & 15)) * GSTRIDE + (lane >> 4) * 4) << 2);
    const uint32_t bAddr0 = smem0 + ((2 * TM * GSTRIDE) << 2) +
        (((wn * 32 + (lane & 7) + ((lane >> 4) << 3)) * GSTRIDE + ((lane >> 3) & 1) * 4) << 2);
    const uint32_t aBufBytes = (TM * GSTRIDE) << 2;
    const uint32_t bBufBytes = (128 * GSTRIDE) << 2;

    const int nsteps = K >> 6;

#pragma unroll
    for (int i = 0; i < TM / 32; i++)
        cp_async16(sAp + i * 32 * GSTRIDE, gA + (size_t)i * 32 * K);
#pragma unroll
    for (int i = 0; i < 4; i++)
        cp_async16(sWp + i * 32 * GSTRIDE, gW + (size_t)i * 32 * K);
    cp_commit();

    float acc[MT][4][4] = {};

    for (int s = 0; s < nsteps; s++) {
        if (s + 1 < nsteps) {
            const int buf = (s + 1) & 1;
            const int k0 = (s + 1) << 6;
#pragma unroll
            for (int i = 0; i < TM / 32; i++)
                cp_async16(sAp + buf * TM * GSTRIDE + i * 32 * GSTRIDE,
                           gA + (size_t)i * 32 * K + k0);
#pragma unroll
            for (int i = 0; i < 4; i++)
                cp_async16(sWp + buf * 128 * GSTRIDE + i * 32 * GSTRIDE,
                           gW + (size_t)i * 32 * K + k0);
            cp_commit();
            cp_wait<1>();
        } else {
            cp_wait<0>();
        }
        __syncthreads();

        const uint32_t aB = aAddr0 + (s & 1) * aBufBytes;
        const uint32_t bB = bAddr0 + (s & 1) * bBufBytes;

#pragma unroll
        for (int ks = 0; ks < 4; ks++) {
            const uint32_t ko = ks * 32;
            uint32_t a[MT][4];
            uint32_t b[4][2];
#pragma unroll
            for (int mt = 0; mt < MT; mt++)
                ldsm_x4(a[mt][0], a[mt][1], a[mt][2], a[mt][3],
                        aB + mt * 16 * GSTRIDE * 4 + ko);
#pragma unroll
            for (int np = 0; np < 2; np++)
                ldsm_x4(b[2 * np][0], b[2 * np][1], b[2 * np + 1][0], b[2 * np + 1][1],
                        bB + np * 16 * GSTRIDE * 4 + ko);
#pragma unroll
            for (int mt = 0; mt < MT; mt++)
#pragma unroll
                for (int nt = 0; nt < 4; nt++)
                    mma_f16(acc[mt][nt], a[mt], b[nt]);
        }
        __syncthreads();
    }

#pragma unroll
    for (int nt = 0; nt < 4; nt++) {
        const int col = bn + wn * 32 + nt * 8 + tig * 2;
        const float2 b2 = *(const float2*)&bias[col];
#pragma unroll
        for (int mt = 0; mt < MT; mt++) {
            const int row0 = bm + wm * (TM / 2) + mt * 16 + grp;
            const int row1 = row0 + 8;
            float2 v0, v1;
            v0.x = acc[mt][nt][0] + b2.x;
            v0.y = acc[mt][nt][1] + b2.y;
            v1.x = acc[mt][nt][2] + b2.x;
            v1.y = acc[mt][nt][3] + b2.y;
            if (EPI == 1) {
                v0.x = 0.5f * v0.x * (1.0f + erff(v0.x * 0.70710678118654752f));
                v0.y = 0.5f * v0.y * (1.0f + erff(v0.y * 0.70710678118654752f));
                v1.x = 0.5f * v1.x * (1.0f + erff(v1.x * 0.70710678118654752f));
                v1.y = 0.5f * v1.y * (1.0f + erff(v1.y * 0.70710678118654752f));
            }
            if (EPI == 3 && col < D_MODEL) {
                const float qs = 0.125f * LOG2E;
                v0.x *= qs; v0.y *= qs;
                v1.x *= qs; v1.y *= qs;
            }
            if (EPI == 2) {
                float* C = (float*)Cv;
                const float2 r0 = *(const float2*)&res[(size_t)row0 * M + col];
                const float2 r1 = *(const float2*)&res[(size_t)row1 * M + col];
                v0.x += r0.x; v0.y += r0.y;
                v1.x += r1.x; v1.y += r1.y;
                *(float2*)&C[(size_t)row0 * M + col] = v0;
                *(float2*)&C[(size_t)row1 * M + col] = v1;
            } else {
                __half* C = (__half*)Cv;
                *(__half2*)&C[(size_t)row0 * M + col] = __floats2half2_rn(v0.x, v0.y);
                *(__half2*)&C[(size_t)row1 * M + col] = __floats2half2_rn(v1.x, v1.y);
            }
        }
    }
}

// ---------------- Flash attention: split-KV x4, fixed-max softmax ----------
#define QT 128
#define KTILE 64
#define NTT (KTILE / 8)      // 8 n-tiles in S phase
#define ATTN_SMEM ((QT * GSTRIDE + 4 * KTILE * GSTRIDE) * 4)   // 55296 B

__global__ __launch_bounds__(256, 3) void attn_h(const __half* __restrict__ qkv,
                                                 __half* __restrict__ opart,
                                                 float* __restrict__ lpart) {
    extern __shared__ uint32_t smu[];
    uint32_t* QP = smu;
    uint32_t* Ks = QP + QT * GSTRIDE;
    uint32_t* Vs = Ks + 2 * KTILE * GSTRIDE;

    const int t = threadIdx.x;
    const int lane = t & 31;
    const int warp = t >> 5;
    const int grp = lane >> 2;
    const int tig = lane & 3;
    const int h = blockIdx.y;
    const int b = blockIdx.z / NSPLIT;
    const int split = blockIdx.z % NSPLIT;
    const int q0 = blockIdx.x * QT;
    const float slopeL = LOG2E / (float)(h + 1);

    const __half* qb = qkv + (size_t)b * SEQ * QKV_LD + h * HD;
    const __half* kb = qb + D_MODEL;
    const __half* vb = qb + 2 * D_MODEL;

    {
        const int row = t >> 1;
        const int cb = (t & 1) * 32;
        const __half* src = qb + (size_t)(q0 + row) * QKV_LD + cb;
        uint32_t* dst = QP + row * GSTRIDE + cb / 2;
        cp_async16(dst + 0,  src + 0);
        cp_async16(dst + 4,  src + 8);
        cp_async16(dst + 8,  src + 16);
        cp_async16(dst + 12, src + 24);
    }
    cp_commit();

    const int srow = t >> 2;
    const int scol = (t & 3) << 4;
    const __half* kg = kb + (size_t)srow * QKV_LD + scol;
    const __half* vg = vb + (size_t)srow * QKV_LD + scol;

#define PREFETCH_KV(GT, BSEL) do {                                              \
        const size_t go = (size_t)(GT) * KTILE * QKV_LD;                        \
        uint32_t* kd = Ks + (BSEL) * KTILE * GSTRIDE + srow * GSTRIDE + scol/2; \
        uint32_t* vd = Vs + (BSEL) * KTILE * GSTRIDE + srow * GSTRIDE + scol/2; \
        cp_async16(kd + 0, kg + go + 0);                                        \
        cp_async16(kd + 4, kg + go + 8);                                        \
        cp_async16(vd + 0, vg + go + 0);                                        \
        cp_async16(vd + 4, vg + go + 8);                                        \
        cp_commit();                                                            \
    } while (0)

    const int ntiles = SEQ / KTILE / NSPLIT;   // 8
    const int g0 = split * ntiles;
    PREFETCH_KV(g0, 0);
    cp_wait<1>();
    __syncthreads();

    uint32_t qa[4][4];
    {
        const uint32_t* qrow = QP + (warp * 16 + grp) * GSTRIDE + tig;
#pragma unroll
        for (int ks = 0; ks < 4; ks++) {
            qa[ks][0] = qrow[ks * 8];
            qa[ks][1] = qrow[ks * 8 + 8 * GSTRIDE];
            qa[ks][2] = qrow[ks * 8 + 4];
            qa[ks][3] = qrow[ks * 8 + 8 * GSTRIDE + 4];
        }
    }

    const uint32_t smem0 = (uint32_t)__cvta_generic_to_shared(smu);
    const uint32_t kAddr0 = smem0 + ((QT * GSTRIDE) << 2) +
        ((((lane & 7) + ((lane >> 4) << 3)) * GSTRIDE + ((lane >> 3) & 1) * 4) << 2);
    const uint32_t vAddr0 = smem0 + (((QT + 2 * KTILE) * GSTRIDE) << 2) +
        (((lane & 15) * GSTRIDE) << 2) + ((lane >> 4) << 4);
    const uint32_t kvBufBytes = (KTILE * GSTRIDE) << 2;

    const float qi0 = (float)(q0 + warp * 16 + grp);
    const float qi1 = qi0 + 8.0f;
    const __half2 qi0h = __float2half2_rn(qi0);
    const __half2 qi1h = __float2half2_rn(qi1);
    const __half2 slope2 = __float2half2_rn(slopeL);
    const __half2 eight2 = __float2half2_rn(8.0f);
    const __half2 m0h = __float2half2_rn(SMAX0);
    const uint32_t bones[2] = {ONES2, ONES2};

    uint32_t o[8][2] = {};
    float l0 = 0.0f, l1 = 0.0f;

    for (int kt = 0; kt < ntiles; kt++) {
        const int g = g0 + kt;
        const int k0 = g * KTILE;
        if (kt + 1 < ntiles) {
            PREFETCH_KV(g + 1, (kt + 1) & 1);
            cp_wait<1>();
        } else {
            cp_wait<0>();
        }
        __syncthreads();

        const uint32_t kB = kAddr0 + (kt & 1) * kvBufBytes;
        const uint32_t vB = vAddr0 + (kt & 1) * kvBufBytes;

        uint32_t sh[NTT][2] = {};
#pragma unroll
        for (int ks = 0; ks < 4; ks++) {
#pragma unroll
            for (int np = 0; np < 4; np++) {
                uint32_t b0, b1, b2, b3;
                ldsm_x4(b0, b1, b2, b3, kB + np * 16 * GSTRIDE * 4 + ks * 32);
                uint32_t bb0[2] = {b0, b1};
                uint32_t bb1[2] = {b2, b3};
                mma_h16(sh[2 * np], qa[ks], bb0);
                mma_h16(sh[2 * np + 1], qa[ks], bb1);
            }
        }

        __half2 kj2 = __floats2half2_rn((float)(k0 + 2 * tig),
                                        (float)(k0 + 2 * tig + 1));
#pragma unroll
        for (int nt = 0; nt < NTT; nt++) {
            const __half2 d0 = __habs2(__hsub2(qi0h, kj2));
            const __half2 d1 = __habs2(__hsub2(qi1h, kj2));
            const __half2 t0 = __hfma2(slope2, d0, m0h);
            const __half2 t1 = __hfma2(slope2, d1, m0h);
            sh[nt][0] = ex2_h2(h2u(__hsub2(u2h(sh[nt][0]), t0)));
            sh[nt][1] = ex2_h2(h2u(__hsub2(u2h(sh[nt][1]), t1)));
            kj2 = __hadd2(kj2, eight2);
        }

        float rs[4] = {};
#pragma unroll
        for (int ks = 0; ks < 4; ks++) {
            uint32_t pa[4];
            pa[0] = sh[2 * ks][0];
            pa[1] = sh[2 * ks][1];
            pa[2] = sh[2 * ks + 1][0];
            pa[3] = sh[2 * ks + 1][1];
            const uint32_t vrow = vB + ks * 16 * GSTRIDE * 4;
#pragma unroll
            for (int np = 0; np < 4; np++) {
                uint32_t b0, b1, b2, b3;
                ldsm_x4_trans(b0, b1, b2, b3, vrow + np * 32);
                uint32_t bb0[2] = {b0, b1};
                uint32_t bb1[2] = {b2, b3};
                mma_h16(o[2 * np], pa, bb0);
                mma_h16(o[2 * np + 1], pa, bb1);
            }
            mma_f16(rs, pa, bones);
        }
        l0 += rs[0];
        l1 += rs[2];
        __syncthreads();
    }

    // epilogue -> fp16 partials (raw u32 stores; o regs are half2 already)
    const int row0 = q0 + warp * 16 + grp;
    __half* obase0 = opart + ((size_t)split * NTOK + b * SEQ + row0) * D_MODEL
                     + h * HD + 2 * tig;
    __half* obase1 = obase0 + (size_t)8 * D_MODEL;
#pragma unroll
    for (int nt = 0; nt < 8; nt++) {
        *(uint32_t*)(obase0 + nt * 8) = o[nt][0];
        *(uint32_t*)(obase1 + nt * 8) = o[nt][1];
    }
    if (tig == 0) {
        float* lb = lpart + (size_t)split * BATCH * NH * SEQ
                    + ((size_t)b * NH + h) * SEQ;
        lb[row0]     = l0;
        lb[row0 + 8] = l1;
    }
}

// ---------------- combine: ctx = sum(O_s) / sum(l_s) -> half ----------------
__global__ __launch_bounds__(256) void combine_k(const __half* __restrict__ opart,
                                                 const float* __restrict__ lpart,
                                                 __half* __restrict__ ctx) {
    const int i = blockIdx.x * 256 + threadIdx.x;   // 8 halves each
    const int base = i * 8;
    const int row = base >> 9;
    const int c = base & 511;
    const int b = row >> 11;
    const int s = row & 2047;
    const int h = c >> 6;
    const size_t li = ((size_t)b * NH + h) * SEQ + s;
    float l = 0.0f;
#pragma unroll
    for (int sp = 0; sp < NSPLIT; sp++)
        l += lpart[(size_t)sp * BATCH * NH * SEQ + li];
    const float inv = 1.0f / l;
    float acc[8] = {};
#pragma unroll
    for (int sp = 0; sp < NSPLIT; sp++) {
        const uint4 d = *(const uint4*)(opart
            + (size_t)(sp * NTOK + row) * D_MODEL + c);
        const float2 f0 = __half22float2(u2h(d.x));
        const float2 f1 = __half22float2(u2h(d.y));
        const float2 f2 = __half22float2(u2h(d.z));
        const float2 f3 = __half22float2(u2h(d.w));
        acc[0] += f0.x; acc[1] += f0.y; acc[2] += f1.x; acc[3] += f1.y;
        acc[4] += f2.x; acc[5] += f2.y; acc[6] += f3.x; acc[7] += f3.y;
    }
    uint4 u;
    u.x = h2u(__floats2half2_rn(acc[0] * inv, acc[1] * inv));
    u.y = h2u(__floats2half2_rn(acc[2] * inv, acc[3] * inv));
    u.z = h2u(__floats2half2_rn(acc[4] * inv, acc[5] * inv));
    u.w = h2u(__floats2half2_rn(acc[6] * inv, acc[7] * inv));
    *(uint4*)(ctx + (size_t)row * D_MODEL + c) = u;
}

// ---------------- launch ----------------
extern "C" void kernel_launch(void* const* d_in, const int* in_sizes, int n_in,
                              void* d_out, int out_size) {
    const float* x    = (const float*)d_in[0];
    const float* n1s  = (const float*)d_in[1];
    const float* n2s  = (const float*)d_in[2];
    const float* wqkv = (const float*)d_in[3];
    const float* bqkv = (const float*)d_in[4];
    const float* wo   = (const float*)d_in[5];
    const float* bo   = (const float*)d_in[6];
    const float* w1   = (const float*)d_in[7];
    const float* b1   = (const float*)d_in[8];
    const float* w2   = (const float*)d_in[9];
    const float* b2   = (const float*)d_in[10];
    float* out = (float*)d_out;

    __half *xn, *qkv, *ctx, *xn2, *hb, *wr, *opart;
    float *x1, *lpart;
    cudaGetSymbolAddress((void**)&xn,  g_xn);
    cudaGetSymbolAddress((void**)&qkv, g_qkv);
    cudaGetSymbolAddress((void**)&ctx, g_ctx);
    cudaGetSymbolAddress((void**)&xn2, g_xn2);
    cudaGetSymbolAddress((void**)&hb,  g_h);
    cudaGetSymbolAddress((void**)&wr,  g_wr);
    cudaGetSymbolAddress((void**)&x1,  g_x1);
    cudaGetSymbolAddress((void**)&opart, g_opart);
    cudaGetSymbolAddress((void**)&lpart, g_lpart);

    const int smem64 = (2 * 64 + 2 * 128) * GSTRIDE * 4;    // 55296
    cudaFuncSetAttribute(attn_h, cudaFuncAttributeMaxDynamicSharedMemorySize, ATTN_SMEM);
    cudaFuncSetAttribute((gemm_h<1,64>), cudaFuncAttributeMaxDynamicSharedMemorySize, smem64);
    cudaFuncSetAttribute((gemm_h<2,64>), cudaFuncAttributeMaxDynamicSharedMemorySize, smem64);
    cudaFuncSetAttribute((gemm_h<3,64>), cudaFuncAttributeMaxDynamicSharedMemorySize, smem64);

    // 0) convert all weights to fp16 (single launch)
    cvtw_all<<<N8_TOT / 256, 256>>>(wqkv, wo, w1, w2, wr);

    // 1) rmsnorm1 -> half
    rmsnorm_k<<<NTOK, 128>>>(x, n1s, xn);
    // 2) qkv projection (q scaled 0.125*log2e) -> half
    gemm_h<3,64><<<dim3(QKV_LD / 128, NTOK / 64), 256, smem64>>>(
        xn, wr + WR_QKV, bqkv, nullptr, qkv, NTOK, QKV_LD, D_MODEL);
    // 3) attention split-KV x4 -> fp16 partials, then combine -> half ctx
    attn_h<<<dim3(SEQ / QT, NH, BATCH * NSPLIT), 256, ATTN_SMEM>>>(qkv, opart, lpart);
    combine_k<<<NTOK * D_MODEL / 8 / 256, 256>>>(opart, lpart, ctx);
    // 4) out projection + residual -> float x1
    gemm_h<2,64><<<dim3(D_MODEL / 128, NTOK / 64), 256, smem64>>>(
        ctx, wr + WR_O, bo, x, x1, NTOK, D_MODEL, D_MODEL);
    // 5) rmsnorm2 -> half
    rmsnorm_k<<<NTOK, 128>>>(x1, n2s, xn2);
    // 6) mlp up + GELU -> half
    gemm_h<1,64><<<dim3(DFF / 128, NTOK / 64), 256, smem64>>>(
        xn2, wr + WR_1, b1, nullptr, hb, NTOK, DFF, D_MODEL);
    // 7) mlp down + residual -> float out
    gemm_h<2,64><<<dim3(D_MODEL / 128, NTOK / 64), 256, smem64>>>(
        hb, wr + WR_2, b2, x1, out, NTOK, D_MODEL, DFF);
}

// round 15
// speedup vs baseline: 1.0645x; 1.0645x over previous
#include <cuda_runtime.h>
#include <cuda_fp16.h>
#include <math.h>
#include <stdint.h>
#include <stddef.h>

#define D_MODEL 512
#define NH      8
#define HD      64
#define DFF     2048
#define BATCH   2
#define SEQ     2048
#define NTOK    (BATCH * SEQ)   // 4096
#define QKV_LD  (3 * D_MODEL)   // 1536
#define NSPLIT  4

// ---------------- scratch (no allocation allowed) ----------------
__device__ __half g_xn [NTOK * D_MODEL];
__device__ __half g_qkv[NTOK * QKV_LD];
__device__ __half g_ctx[NTOK * D_MODEL];
__device__ __half g_xn2[NTOK * D_MODEL];
__device__ __half g_h  [NTOK * DFF];
__device__ float  g_x1 [NTOK * D_MODEL];
__device__ __half g_opart[NSPLIT * NTOK * D_MODEL];   // split-KV partial O (fp16)
__device__ float  g_lpart[NSPLIT * BATCH * NH * SEQ]; // split-KV partial l
// converted (fp16) weights: wqkv | wo | w1 | w2
#define WR_QKV 0
#define WR_O   (QKV_LD * D_MODEL)
#define WR_1   (WR_O + D_MODEL * D_MODEL)
#define WR_2   (WR_1 + DFF * D_MODEL)
#define WR_TOT (WR_2 + D_MODEL * DFF)
__device__ __half g_wr[WR_TOT];

#define LOG2E 1.4426950408889634f
#define ONES2 0x3C003C00u   // half2(1.0, 1.0)
#define SMAX0 3.0f          // fixed softmax max (exp2 domain); cancels in O/l

// ---------------- helpers ----------------
__device__ __forceinline__ uint32_t h2u(__half2 h) {
    return *reinterpret_cast<uint32_t*>(&h);
}
__device__ __forceinline__ __half2 u2h(uint32_t u) {
    return *reinterpret_cast<__half2*>(&u);
}

__device__ __forceinline__ void mma_f16(float (&d)[4], const uint32_t (&a)[4],
                                        const uint32_t (&b)[2]) {
    asm volatile(
        "mma.sync.aligned.m16n8k16.row.col.f32.f16.f16.f32 "
        "{%0,%1,%2,%3}, {%4,%5,%6,%7}, {%8,%9}, {%0,%1,%2,%3};\n"
        : "+f"(d[0]), "+f"(d[1]), "+f"(d[2]), "+f"(d[3])
        : "r"(a[0]), "r"(a[1]), "r"(a[2]), "r"(a[3]), "r"(b[0]), "r"(b[1]));
}

__device__ __forceinline__ void mma_h16(uint32_t (&d)[2], const uint32_t (&a)[4],
                                        const uint32_t (&b)[2]) {
    asm volatile(
        "mma.sync.aligned.m16n8k16.row.col.f16.f16.f16.f16 "
        "{%0,%1}, {%2,%3,%4,%5}, {%6,%7}, {%0,%1};\n"
        : "+r"(d[0]), "+r"(d[1])
        : "r"(a[0]), "r"(a[1]), "r"(a[2]), "r"(a[3]), "r"(b[0]), "r"(b[1]));
}

__device__ __forceinline__ void ldsm_x4(uint32_t& r0, uint32_t& r1, uint32_t& r2,
                                        uint32_t& r3, uint32_t addr) {
    asm volatile("ldmatrix.sync.aligned.m8n8.x4.shared.b16 {%0,%1,%2,%3}, [%4];\n"
                 : "=r"(r0), "=r"(r1), "=r"(r2), "=r"(r3) : "r"(addr));
}

__device__ __forceinline__ void ldsm_x4_trans(uint32_t& r0, uint32_t& r1, uint32_t& r2,
                                              uint32_t& r3, uint32_t addr) {
    asm volatile("ldmatrix.sync.aligned.m8n8.x4.trans.shared.b16 {%0,%1,%2,%3}, [%4];\n"
                 : "=r"(r0), "=r"(r1), "=r"(r2), "=r"(r3) : "r"(addr));
}

__device__ __forceinline__ uint32_t ex2_h2(uint32_t x) {
    uint32_t r;
    asm("ex2.approx.f16x2 %0, %1;\n" : "=r"(r) : "r"(x));
    return r;
}

__device__ __forceinline__ void cp_async16(void* smem_dst, const void* gsrc) {
    uint32_t s = (uint32_t)__cvta_generic_to_shared(smem_dst);
    asm volatile("cp.async.cg.shared.global [%0], [%1], 16;\n" :: "r"(s), "l"(gsrc));
}
__device__ __forceinline__ void cp_commit() {
    asm volatile("cp.async.commit_group;\n");
}
template <int N>
__device__ __forceinline__ void cp_wait() {
    asm volatile("cp.async.wait_group %0;\n" :: "n"(N));
}

// ---------------- fused weight f32 -> f16 (all 4 weights, 1 launch) --------
#define N8_QKV (QKV_LD * D_MODEL / 8)
#define N8_O   (D_MODEL * D_MODEL / 8)
#define N8_1   (DFF * D_MODEL / 8)
#define N8_2   (D_MODEL * DFF / 8)
#define N8_TOT (N8_QKV + N8_O + N8_1 + N8_2)   // 393216 = 1536*256

__global__ __launch_bounds__(256) void cvtw_all(const float* __restrict__ wqkv,
                                                const float* __restrict__ wo,
                                                const float* __restrict__ w1,
                                                const float* __restrict__ w2,
                                                __half* __restrict__ d) {
    const int i = blockIdx.x * 256 + threadIdx.x;
    int j = i;
    const float* s;
    if (j < N8_QKV) { s = wqkv; }
    else {
        j -= N8_QKV;
        if (j < N8_O) { s = wo; }
        else {
            j -= N8_O;
            if (j < N8_1) { s = w1; }
            else { j -= N8_1; s = w2; }
        }
    }
    const float4 v0 = ((const float4*)s)[2 * j];
    const float4 v1 = ((const float4*)s)[2 * j + 1];
    uint4 o;
    o.x = h2u(__floats2half2_rn(v0.x, v0.y));
    o.y = h2u(__floats2half2_rn(v0.z, v0.w));
    o.z = h2u(__floats2half2_rn(v1.x, v1.y));
    o.w = h2u(__floats2half2_rn(v1.z, v1.w));
    ((uint4*)d)[i] = o;
}

// ---------------- RMSNorm: f32 in, f16 out ----------------
__global__ __launch_bounds__(128) void rmsnorm_k(const float* __restrict__ x,
                                                 const float* __restrict__ sc,
                                                 __half* __restrict__ o) {
    const int row = blockIdx.x;
    const int t = threadIdx.x;
    const float4 v = ((const float4*)(x + (size_t)row * D_MODEL))[t];
    float ss = v.x * v.x + v.y * v.y + v.z * v.z + v.w * v.w;
#pragma unroll
    for (int ofs = 16; ofs; ofs >>= 1)
        ss += __shfl_xor_sync(0xffffffffu, ss, ofs);
    __shared__ float ws[4];
    if ((t & 31) == 0) ws[t >> 5] = ss;
    __syncthreads();
    const float tot = ws[0] + ws[1] + ws[2] + ws[3];
    const float r = rsqrtf(tot * (1.0f / D_MODEL) + 1e-8f);
    const float4 s4 = ((const float4*)sc)[t];
    uint2 u;
    u.x = h2u(__floats2half2_rn(v.x * s4.x * r, v.y * s4.y * r));
    u.y = h2u(__floats2half2_rn(v.z * s4.z * r, v.w * s4.w * r));
    ((uint2*)(o + (size_t)row * D_MODEL))[t] = u;
}

// ---------------- FP16 tensor-core GEMM, ldmatrix fragments ----------------
// C[N,M] = A[N,K] @ W[M,K]^T + bias. Block tile 128x128x64.
// EPI: 1 = GELU -> half, 2 = +res -> float, 3 = qkv (scale q cols) -> half
#define GSTRIDE 36   // uint32 (half2) units per row: 32 data + 4 pad
#define GEMM_SMEM (4 * 128 * GSTRIDE * 4)   // 73728 B
template <int EPI>
__global__ __launch_bounds__(256, 2) void gemm_h(const __half* __restrict__ A,
                                                 const __half* __restrict__ W,
                                                 const float* __restrict__ bias,
                                                 const float* __restrict__ res,
                                                 void* __restrict__ Cv,
                                                 int N, int M, int K) {
    extern __shared__ uint32_t smu[];

    const int t = threadIdx.x;
    const int lane = t & 31;
    const int warp = t >> 5;
    const int wm = warp & 1;
    const int wn = warp >> 1;
    const int grp = lane >> 2;
    const int tig = lane & 3;

    const int bm = blockIdx.y * 128;
    const int bn = blockIdx.x * 128;

    const int crow = t >> 3;
    const int cchk = t & 7;
    const __half* gA = A + (size_t)(bm + crow) * K + cchk * 8;
    const __half* gW = W + (size_t)(bn + crow) * K + cchk * 8;
    uint32_t* sAp = smu + crow * GSTRIDE + cchk * 4;
    uint32_t* sWp = smu + 2 * 128 * GSTRIDE + crow * GSTRIDE + cchk * 4;

    const uint32_t smem0 = (uint32_t)__cvta_generic_to_shared(smu);
    const uint32_t aAddr0 = smem0 +
        (((wm * 64 + (lane & 15)) * GSTRIDE + (lane >> 4) * 4) << 2);
    const uint32_t bAddr0 = smem0 + ((2 * 128 * GSTRIDE) << 2) +
        (((wn * 32 + (lane & 7) + ((lane >> 4) << 3)) * GSTRIDE + ((lane >> 3) & 1) * 4) << 2);
    const uint32_t bufBytes = (128 * GSTRIDE) << 2;

    const int nsteps = K >> 6;

#pragma unroll
    for (int i = 0; i < 4; i++) {
        cp_async16(sAp + i * 32 * GSTRIDE, gA + (size_t)i * 32 * K);
        cp_async16(sWp + i * 32 * GSTRIDE, gW + (size_t)i * 32 * K);
    }
    cp_commit();

    float acc[4][4][4] = {};

    for (int s = 0; s < nsteps; s++) {
        if (s + 1 < nsteps) {
            const int buf = (s + 1) & 1;
            const int k0 = (s + 1) << 6;
#pragma unroll
            for (int i = 0; i < 4; i++) {
                cp_async16(sAp + buf * 128 * GSTRIDE + i * 32 * GSTRIDE,
                           gA + (size_t)i * 32 * K + k0);
                cp_async16(sWp + buf * 128 * GSTRIDE + i * 32 * GSTRIDE,
                           gW + (size_t)i * 32 * K + k0);
            }
            cp_commit();
            cp_wait<1>();
        } else {
            cp_wait<0>();
        }
        __syncthreads();

        const uint32_t aB = aAddr0 + (s & 1) * bufBytes;
        const uint32_t bB = bAddr0 + (s & 1) * bufBytes;

#pragma unroll
        for (int ks = 0; ks < 4; ks++) {
            const uint32_t ko = ks * 32;
            uint32_t a[4][4];
            uint32_t b[4][2];
#pragma unroll
            for (int mt = 0; mt < 4; mt++)
                ldsm_x4(a[mt][0], a[mt][1], a[mt][2], a[mt][3],
                        aB + mt * 16 * GSTRIDE * 4 + ko);
#pragma unroll
            for (int np = 0; np < 2; np++)
                ldsm_x4(b[2 * np][0], b[2 * np][1], b[2 * np + 1][0], b[2 * np + 1][1],
                        bB + np * 16 * GSTRIDE * 4 + ko);
#pragma unroll
            for (int mt = 0; mt < 4; mt++)
#pragma unroll
                for (int nt = 0; nt < 4; nt++)
                    mma_f16(acc[mt][nt], a[mt], b[nt]);
        }
        __syncthreads();
    }

#pragma unroll
    for (int nt = 0; nt < 4; nt++) {
        const int col = bn + wn * 32 + nt * 8 + tig * 2;
        const float2 b2 = *(const float2*)&bias[col];
#pragma unroll
        for (int mt = 0; mt < 4; mt++) {
            const int row0 = bm + wm * 64 + mt * 16 + grp;
            const int row1 = row0 + 8;
            float2 v0, v1;
            v0.x = acc[mt][nt][0] + b2.x;
            v0.y = acc[mt][nt][1] + b2.y;
            v1.x = acc[mt][nt][2] + b2.x;
            v1.y = acc[mt][nt][3] + b2.y;
            if (EPI == 1) {
                v0.x = 0.5f * v0.x * (1.0f + erff(v0.x * 0.70710678118654752f));
                v0.y = 0.5f * v0.y * (1.0f + erff(v0.y * 0.70710678118654752f));
                v1.x = 0.5f * v1.x * (1.0f + erff(v1.x * 0.70710678118654752f));
                v1.y = 0.5f * v1.y * (1.0f + erff(v1.y * 0.70710678118654752f));
            }
            if (EPI == 3 && col < D_MODEL) {
                const float qs = 0.125f * LOG2E;
                v0.x *= qs; v0.y *= qs;
                v1.x *= qs; v1.y *= qs;
            }
            if (EPI == 2) {
                float* C = (float*)Cv;
                const float2 r0 = *(const float2*)&res[(size_t)row0 * M + col];
                const float2 r1 = *(const float2*)&res[(size_t)row1 * M + col];
                v0.x += r0.x; v0.y += r0.y;
                v1.x += r1.x; v1.y += r1.y;
                *(float2*)&C[(size_t)row0 * M + col] = v0;
                *(float2*)&C[(size_t)row1 * M + col] = v1;
            } else {
                __half* C = (__half*)Cv;
                *(__half2*)&C[(size_t)row0 * M + col] = __floats2half2_rn(v0.x, v0.y);
                *(__half2*)&C[(size_t)row1 * M + col] = __floats2half2_rn(v1.x, v1.y);
            }
        }
    }
}

// ---------------- Flash attention: split-KV x4, fixed-max softmax ----------
#define QT 128
#define KTILE 64
#define NTT (KTILE / 8)      // 8 n-tiles in S phase
#define ATTN_SMEM ((QT * GSTRIDE + 4 * KTILE * GSTRIDE) * 4)   // 55296 B

__global__ __launch_bounds__(256, 3) void attn_h(const __half* __restrict__ qkv,
                                                 __half* __restrict__ opart,
                                                 float* __restrict__ lpart) {
    extern __shared__ uint32_t smu[];
    uint32_t* QP = smu;
    uint32_t* Ks = QP + QT * GSTRIDE;
    uint32_t* Vs = Ks + 2 * KTILE * GSTRIDE;

    const int t = threadIdx.x;
    const int lane = t & 31;
    const int warp = t >> 5;
    const int grp = lane >> 2;
    const int tig = lane & 3;
    const int h = blockIdx.y;
    const int b = blockIdx.z / NSPLIT;
    const int split = blockIdx.z % NSPLIT;
    const int q0 = blockIdx.x * QT;
    const float slopeL = LOG2E / (float)(h + 1);

    const __half* qb = qkv + (size_t)b * SEQ * QKV_LD + h * HD;
    const __half* kb = qb + D_MODEL;
    const __half* vb = qb + 2 * D_MODEL;

    {
        const int row = t >> 1;
        const int cb = (t & 1) * 32;
        const __half* src = qb + (size_t)(q0 + row) * QKV_LD + cb;
        uint32_t* dst = QP + row * GSTRIDE + cb / 2;
        cp_async16(dst + 0,  src + 0);
        cp_async16(dst + 4,  src + 8);
        cp_async16(dst + 8,  src + 16);
        cp_async16(dst + 12, src + 24);
    }
    cp_commit();

    const int srow = t >> 2;
    const int scol = (t & 3) << 4;
    const __half* kg = kb + (size_t)srow * QKV_LD + scol;
    const __half* vg = vb + (size_t)srow * QKV_LD + scol;

#define PREFETCH_KV(GT, BSEL) do {                                              \
        const size_t go = (size_t)(GT) * KTILE * QKV_LD;                        \
        uint32_t* kd = Ks + (BSEL) * KTILE * GSTRIDE + srow * GSTRIDE + scol/2; \
        uint32_t* vd = Vs + (BSEL) * KTILE * GSTRIDE + srow * GSTRIDE + scol/2; \
        cp_async16(kd + 0, kg + go + 0);                                        \
        cp_async16(kd + 4, kg + go + 8);                                        \
        cp_async16(vd + 0, vg + go + 0);                                        \
        cp_async16(vd + 4, vg + go + 8);                                        \
        cp_commit();                                                            \
    } while (0)

    const int ntiles = SEQ / KTILE / NSPLIT;   // 8
    const int g0 = split * ntiles;
    PREFETCH_KV(g0, 0);
    cp_wait<1>();
    __syncthreads();

    uint32_t qa[4][4];
    {
        const uint32_t* qrow = QP + (warp * 16 + grp) * GSTRIDE + tig;
#pragma unroll
        for (int ks = 0; ks < 4; ks++) {
            qa[ks][0] = qrow[ks * 8];
            qa[ks][1] = qrow[ks * 8 + 8 * GSTRIDE];
            qa[ks][2] = qrow[ks * 8 + 4];
            qa[ks][3] = qrow[ks * 8 + 8 * GSTRIDE + 4];
        }
    }

    const uint32_t smem0 = (uint32_t)__cvta_generic_to_shared(smu);
    const uint32_t kAddr0 = smem0 + ((QT * GSTRIDE) << 2) +
        ((((lane & 7) + ((lane >> 4) << 3)) * GSTRIDE + ((lane >> 3) & 1) * 4) << 2);
    const uint32_t vAddr0 = smem0 + (((QT + 2 * KTILE) * GSTRIDE) << 2) +
        (((lane & 15) * GSTRIDE) << 2) + ((lane >> 4) << 4);
    const uint32_t kvBufBytes = (KTILE * GSTRIDE) << 2;

    const float qi0 = (float)(q0 + warp * 16 + grp);
    const float qi1 = qi0 + 8.0f;
    const __half2 qi0h = __float2half2_rn(qi0);
    const __half2 qi1h = __float2half2_rn(qi1);
    const __half2 slope2 = __float2half2_rn(slopeL);
    const __half2 eight2 = __float2half2_rn(8.0f);
    const __half2 m0h = __float2half2_rn(SMAX0);
    const uint32_t bones[2] = {ONES2, ONES2};

    uint32_t o[8][2] = {};
    float l0 = 0.0f, l1 = 0.0f;

    for (int kt = 0; kt < ntiles; kt++) {
        const int g = g0 + kt;
        const int k0 = g * KTILE;
        if (kt + 1 < ntiles) {
            PREFETCH_KV(g + 1, (kt + 1) & 1);
            cp_wait<1>();
        } else {
            cp_wait<0>();
        }
        __syncthreads();

        const uint32_t kB = kAddr0 + (kt & 1) * kvBufBytes;
        const uint32_t vB = vAddr0 + (kt & 1) * kvBufBytes;

        uint32_t sh[NTT][2] = {};
#pragma unroll
        for (int ks = 0; ks < 4; ks++) {
#pragma unroll
            for (int np = 0; np < 4; np++) {
                uint32_t b0, b1, b2, b3;
                ldsm_x4(b0, b1, b2, b3, kB + np * 16 * GSTRIDE * 4 + ks * 32);
                uint32_t bb0[2] = {b0, b1};
                uint32_t bb1[2] = {b2, b3};
                mma_h16(sh[2 * np], qa[ks], bb0);
                mma_h16(sh[2 * np + 1], qa[ks], bb1);
            }
        }

        __half2 kj2 = __floats2half2_rn((float)(k0 + 2 * tig),
                                        (float)(k0 + 2 * tig + 1));
#pragma unroll
        for (int nt = 0; nt < NTT; nt++) {
            const __half2 d0 = __habs2(__hsub2(qi0h, kj2));
            const __half2 d1 = __habs2(__hsub2(qi1h, kj2));
            const __half2 t0 = __hfma2(slope2, d0, m0h);
            const __half2 t1 = __hfma2(slope2, d1, m0h);
            sh[nt][0] = ex2_h2(h2u(__hsub2(u2h(sh[nt][0]), t0)));
            sh[nt][1] = ex2_h2(h2u(__hsub2(u2h(sh[nt][1]), t1)));
            kj2 = __hadd2(kj2, eight2);
        }

        float rs[4] = {};
#pragma unroll
        for (int ks = 0; ks < 4; ks++) {
            uint32_t pa[4];
            pa[0] = sh[2 * ks][0];
            pa[1] = sh[2 * ks][1];
            pa[2] = sh[2 * ks + 1][0];
            pa[3] = sh[2 * ks + 1][1];
            const uint32_t vrow = vB + ks * 16 * GSTRIDE * 4;
#pragma unroll
            for (int np = 0; np < 4; np++) {
                uint32_t b0, b1, b2, b3;
                ldsm_x4_trans(b0, b1, b2, b3, vrow + np * 32);
                uint32_t bb0[2] = {b0, b1};
                uint32_t bb1[2] = {b2, b3};
                mma_h16(o[2 * np], pa, bb0);
                mma_h16(o[2 * np + 1], pa, bb1);
            }
            mma_f16(rs, pa, bones);
        }
        l0 += rs[0];
        l1 += rs[2];
        __syncthreads();
    }

    // epilogue -> fp16 partials (raw u32 stores)
    const int row0 = q0 + warp * 16 + grp;
    __half* obase0 = opart + ((size_t)split * NTOK + b * SEQ + row0) * D_MODEL
                     + h * HD + 2 * tig;
    __half* obase1 = obase0 + (size_t)8 * D_MODEL;
#pragma unroll
    for (int nt = 0; nt < 8; nt++) {
        *(uint32_t*)(obase0 + nt * 8) = o[nt][0];
        *(uint32_t*)(obase1 + nt * 8) = o[nt][1];
    }
    if (tig == 0) {
        float* lb = lpart + (size_t)split * BATCH * NH * SEQ
                    + ((size_t)b * NH + h) * SEQ;
        lb[row0]     = l0;
        lb[row0 + 8] = l1;
    }
}

// ---------------- combine: ctx = sum(O_s) / sum(l_s) -> half ----------------
__global__ __launch_bounds__(256) void combine_k(const __half* __restrict__ opart,
                                                 const float* __restrict__ lpart,
                                                 __half* __restrict__ ctx) {
    const int i = blockIdx.x * 256 + threadIdx.x;   // 8 halves each
    const int base = i * 8;
    const int row = base >> 9;
    const int c = base & 511;
    const int b = row >> 11;
    const int s = row & 2047;
    const int h = c >> 6;
    const size_t li = ((size_t)b * NH + h) * SEQ + s;
    float l = 0.0f;
#pragma unroll
    for (int sp = 0; sp < NSPLIT; sp++)
        l += lpart[(size_t)sp * BATCH * NH * SEQ + li];
    const float inv = 1.0f / l;
    float acc[8] = {};
#pragma unroll
    for (int sp = 0; sp < NSPLIT; sp++) {
        const uint4 d = *(const uint4*)(opart
            + (size_t)(sp * NTOK + row) * D_MODEL + c);
        const float2 f0 = __half22float2(u2h(d.x));
        const float2 f1 = __half22float2(u2h(d.y));
        const float2 f2 = __half22float2(u2h(d.z));
        const float2 f3 = __half22float2(u2h(d.w));
        acc[0] += f0.x; acc[1] += f0.y; acc[2] += f1.x; acc[3] += f1.y;
        acc[4] += f2.x; acc[5] += f2.y; acc[6] += f3.x; acc[7] += f3.y;
    }
    uint4 u;
    u.x = h2u(__floats2half2_rn(acc[0] * inv, acc[1] * inv));
    u.y = h2u(__floats2half2_rn(acc[2] * inv, acc[3] * inv));
    u.z = h2u(__floats2half2_rn(acc[4] * inv, acc[5] * inv));
    u.w = h2u(__floats2half2_rn(acc[6] * inv, acc[7] * inv));
    *(uint4*)(ctx + (size_t)row * D_MODEL + c) = u;
}

// ---------------- launch ----------------
extern "C" void kernel_launch(void* const* d_in, const int* in_sizes, int n_in,
                              void* d_out, int out_size) {
    const float* x    = (const float*)d_in[0];
    const float* n1s  = (const float*)d_in[1];
    const float* n2s  = (const float*)d_in[2];
    const float* wqkv = (const float*)d_in[3];
    const float* bqkv = (const float*)d_in[4];
    const float* wo   = (const float*)d_in[5];
    const float* bo   = (const float*)d_in[6];
    const float* w1   = (const float*)d_in[7];
    const float* b1   = (const float*)d_in[8];
    const float* w2   = (const float*)d_in[9];
    const float* b2   = (const float*)d_in[10];
    float* out = (float*)d_out;

    __half *xn, *qkv, *ctx, *xn2, *hb, *wr, *opart;
    float *x1, *lpart;
    cudaGetSymbolAddress((void**)&xn,  g_xn);
    cudaGetSymbolAddress((void**)&qkv, g_qkv);
    cudaGetSymbolAddress((void**)&ctx, g_ctx);
    cudaGetSymbolAddress((void**)&xn2, g_xn2);
    cudaGetSymbolAddress((void**)&hb,  g_h);
    cudaGetSymbolAddress((void**)&wr,  g_wr);
    cudaGetSymbolAddress((void**)&x1,  g_x1);
    cudaGetSymbolAddress((void**)&opart, g_opart);
    cudaGetSymbolAddress((void**)&lpart, g_lpart);

    cudaFuncSetAttribute(attn_h, cudaFuncAttributeMaxDynamicSharedMemorySize, ATTN_SMEM);
    cudaFuncSetAttribute(gemm_h<1>, cudaFuncAttributeMaxDynamicSharedMemorySize, GEMM_SMEM);
    cudaFuncSetAttribute(gemm_h<2>, cudaFuncAttributeMaxDynamicSharedMemorySize, GEMM_SMEM);
    cudaFuncSetAttribute(gemm_h<3>, cudaFuncAttributeMaxDynamicSharedMemorySize, GEMM_SMEM);

    // 0) convert all weights to fp16 (single launch)
    cvtw_all<<<N8_TOT / 256, 256>>>(wqkv, wo, w1, w2, wr);

    // 1) rmsnorm1 -> half
    rmsnorm_k<<<NTOK, 128>>>(x, n1s, xn);
    // 2) qkv projection (q scaled 0.125*log2e) -> half
    gemm_h<3><<<dim3(QKV_LD / 128, NTOK / 128), 256, GEMM_SMEM>>>(
        xn, wr + WR_QKV, bqkv, nullptr, qkv, NTOK, QKV_LD, D_MODEL);
    // 3) attention split-KV x4 -> fp16 partials, then combine -> half ctx
    attn_h<<<dim3(SEQ / QT, NH, BATCH * NSPLIT), 256, ATTN_SMEM>>>(qkv, opart, lpart);
    combine_k<<<NTOK * D_MODEL / 8 / 256, 256>>>(opart, lpart, ctx);
    // 4) out projection + residual -> float x1
    gemm_h<2><<<dim3(D_MODEL / 128, NTOK / 128), 256, GEMM_SMEM>>>(
        ctx, wr + WR_O, bo, x, x1, NTOK, D_MODEL, D_MODEL);
    // 5) rmsnorm2 -> half
    rmsnorm_k<<<NTOK, 128>>>(x1, n2s, xn2);
    // 6) mlp up + GELU -> half
    gemm_h<1><<<dim3(DFF / 128, NTOK / 128), 256, GEMM_SMEM>>>(
        xn2, wr + WR_1, b1, nullptr, hb, NTOK, DFF, D_MODEL);
    // 7) mlp down + residual -> float out
    gemm_h<2><<<dim3(D_MODEL / 128, NTOK / 128), 256, GEMM_SMEM>>>(
        hb, wr + WR_2, b2, x1, out, NTOK, D_MODEL, DFF);
}